// round 2
// baseline (speedup 1.0000x reference)
#include <cuda_runtime.h>

// Fixed problem shape: B=1, T=4, V=6, H=128, W=128
#define MAXID    8192
#define BT       4
#define M_ELEMS  393216
#define VHW      (M_ELEMS / BT)       // 98304
#define NSEGS    (BT * MAXID)         // 32768 real segments (dummy excluded)
#define REC      112                  // padded per-segment record (floats)
#define NEGF     (-1e30f)
#define THRF     2.0f
#define DUPF     0.05f
#define FULL     0xffffffffu

// Per-segment record layout (float slots):
//  [0..63] dense  [64..79] inst  [80..87] motion  [88..91] rot
//  [92..94] center [95..97] offset [98] opacity [99..101] scale
//  [102..104] feat_dc [105] dyn

__device__ int           g_counts[NSEGS];
__device__ int           g_start[NSEGS];
__device__ int           g_cur[NSEGS];
__device__ int           g_idx[M_ELEMS];
__device__ float         g_mx2[NSEGS];
__device__ int           g_min[NSEGS];
__device__ unsigned char g_act[M_ELEMS];
__device__ __align__(16) float g_sums[(size_t)NSEGS * REC];

__device__ __forceinline__ float wmaxf(float v) {
#pragma unroll
    for (int o = 16; o; o >>= 1) v = fmaxf(v, __shfl_xor_sync(FULL, v, o));
    return v;
}
__device__ __forceinline__ float wsumf(float v) {
#pragma unroll
    for (int o = 16; o; o >>= 1) v += __shfl_xor_sync(FULL, v, o);
    return v;
}
__device__ __forceinline__ int wmini(int v) {
#pragma unroll
    for (int o = 16; o; o >>= 1) v = min(v, __shfl_xor_sync(FULL, v, o));
    return v;
}

// ---------------- Pass 0: zero counters ----------------
__global__ void k_zero() {
    int t = blockIdx.x * blockDim.x + threadIdx.x;
    if (t < NSEGS) g_counts[t] = 0;
}

// ---------------- Pass 1: count per segment + clear act ----------------
__global__ void k_count(const int* __restrict__ ids) {
    int i = blockIdx.x * blockDim.x + threadIdx.x;
    if (i >= M_ELEMS) return;
    g_act[i] = 0;
    int id = ids[i];
    if (id >= 0) atomicAdd(&g_counts[(i / VHW) * MAXID + id], 1);
}

// ---------------- Pass 2: exclusive scan (single block) ----------------
__global__ void k_scan() {
    __shared__ int sh[1024];
    const int CH = NSEGS / 1024;   // 32
    int t = threadIdx.x;
    int base = t * CH;
    int loc[CH];
    int sum = 0;
#pragma unroll
    for (int j = 0; j < CH; j++) { loc[j] = g_counts[base + j]; sum += loc[j]; }
    sh[t] = sum;
    __syncthreads();
    for (int o = 1; o < 1024; o <<= 1) {
        int v = (t >= o) ? sh[t - o] : 0;
        __syncthreads();
        sh[t] += v;
        __syncthreads();
    }
    int run = sh[t] - sum;   // exclusive prefix
#pragma unroll
    for (int j = 0; j < CH; j++) {
        g_start[base + j] = run;
        g_cur[base + j]   = run;
        run += loc[j];
    }
}

// ---------------- Pass 3: scatter indices into CSR ----------------
__global__ void k_scatter(const int* __restrict__ ids) {
    int i = blockIdx.x * blockDim.x + threadIdx.x;
    if (i >= M_ELEMS) return;
    int id = ids[i];
    if (id >= 0) {
        int s = (i / VHW) * MAXID + id;
        int pos = atomicAdd(&g_cur[s], 1);
        g_idx[pos] = i;
    }
}

// per-lane channel->pointer map for slots 2 and 3
__device__ __forceinline__ void lane_map(int lane,
        const float* inst, const float* mot, const float* rot,
        const float* cen,  const float* off, const float* opa,
        const float* sca,  const float* fdc, const float* dyn,
        const float*& p2, int& st2, const float*& p3, int& st3) {
    if      (lane < 16) { p2 = inst + lane;      st2 = 16; }
    else if (lane < 24) { p2 = mot + (lane - 16); st2 = 8; }
    else if (lane < 28) { p2 = rot + (lane - 24); st2 = 4; }
    else if (lane < 31) { p2 = cen + (lane - 28); st2 = 3; }
    else                { p2 = off;               st2 = 3; }
    if      (lane < 2)  { p3 = off + (lane + 1);  st3 = 3; }
    else if (lane == 2) { p3 = opa;               st3 = 1; }
    else if (lane < 6)  { p3 = sca + (lane - 3);  st3 = 3; }
    else if (lane < 9)  { p3 = fdc + (lane - 6);  st3 = 3; }
    else if (lane == 9) { p3 = dyn;               st3 = 1; }
    else                { p3 = dyn;               st3 = 0; }  // dummy, never stored
}

// ---------------- Pass 4: warp-per-segment merge ----------------
__global__ void k_merge(const float* __restrict__ dense, const float* __restrict__ cen,
                        const float* __restrict__ off,   const float* __restrict__ opa,
                        const float* __restrict__ sca,   const float* __restrict__ rot,
                        const float* __restrict__ fdc,   const float* __restrict__ kp,
                        const float* __restrict__ inst,  const float* __restrict__ mot,
                        const float* __restrict__ dyn) {
    int warp = (blockIdx.x * blockDim.x + threadIdx.x) >> 5;
    int lane = threadIdx.x & 31;
    if (warp >= NSEGS) return;
    int s = warp;
    int cntv = g_counts[s];
    if (cntv < 2) {
        // cnt<2 => no element can be active; g_act already 0
        return;
    }
    int start = g_start[s];

    float a0 = 0.f, a1 = 0.f, a2 = 0.f, a3 = 0.f;
    float mx2, d2;
    int   mi;
    unsigned actmask = 0;

    const float* p2; int st2; const float* p3; int st3;
    lane_map(lane, inst, mot, rot, cen, off, opa, sca, fdc, dyn, p2, st2, p3, st3);

    if (cntv <= 32) {
        // ---- fast path: whole segment in registers ----
        bool has = lane < cntv;
        int   i = 0;
        float k = NEGF, cx = 0.f, cy = 0.f, cz = 0.f;
        if (has) {
            i = g_idx[start + lane];
            k = kp[i];
            cx = cen[3 * (size_t)i + 0];
            cy = cen[3 * (size_t)i + 1];
            cz = cen[3 * (size_t)i + 2];
        }
        float mx1 = wmaxf(k);
        float e1 = has ? expf(k - mx1) : 0.f;
        float d1 = wsumf(e1);
        float sx = wsumf(cx * e1);
        float sy = wsumf(cy * e1);
        float sz = wsumf(cz * e1);
        float inv1 = (d1 > 0.f) ? (1.f / d1) : 1.f;
        float mcx = sx * inv1, mcy = sy * inv1, mcz = sz * inv1;

        bool act = false;
        if (has) {
            float dx = cx - mcx, dy = cy - mcy, dz = cz - mcz;
            float dist = sqrtf(dx * dx + dy * dy + dz * dz);
            act = dist <= THRF;
            g_act[i] = act ? 1 : 0;
        }
        mx2 = wmaxf(act ? k : NEGF);
        float e2 = act ? expf(k - mx2) : 0.f;
        d2 = wsumf(e2);
        mi = wmini((act && k >= mx2) ? i : M_ELEMS);
        actmask = __ballot_sync(FULL, act);
        if (!actmask) return;

        unsigned m = actmask;
        while (m) {
            int j = __ffs(m) - 1; m &= m - 1;
            int   ib = __shfl_sync(FULL, i, j);
            float w  = __shfl_sync(FULL, e2, j);
            a0 = fmaf(__ldg(dense + (size_t)ib * 64 + lane),      w, a0);
            a1 = fmaf(__ldg(dense + (size_t)ib * 64 + 32 + lane), w, a1);
            a2 = fmaf(__ldg(p2 + (size_t)ib * st2), w, a2);
            a3 = fmaf(__ldg(p3 + (size_t)ib * st3), w, a3);
        }
    } else {
        // ---- generic path (rare; count > 32) ----
        float mx1 = NEGF;
        for (int b = lane; b < cntv; b += 32) {
            int ii = g_idx[start + b];
            mx1 = fmaxf(mx1, kp[ii]);
        }
        mx1 = wmaxf(mx1);
        float d1 = 0.f, sx = 0.f, sy = 0.f, sz = 0.f;
        for (int b = lane; b < cntv; b += 32) {
            int ii = g_idx[start + b];
            float e = expf(kp[ii] - mx1);
            d1 += e;
            sx += cen[3 * (size_t)ii + 0] * e;
            sy += cen[3 * (size_t)ii + 1] * e;
            sz += cen[3 * (size_t)ii + 2] * e;
        }
        d1 = wsumf(d1); sx = wsumf(sx); sy = wsumf(sy); sz = wsumf(sz);
        float inv1 = (d1 > 0.f) ? (1.f / d1) : 1.f;
        float mcx = sx * inv1, mcy = sy * inv1, mcz = sz * inv1;

        float lmx2 = NEGF;
        for (int b = lane; b < cntv; b += 32) {
            int ii = g_idx[start + b];
            float dx = cen[3 * (size_t)ii + 0] - mcx;
            float dy = cen[3 * (size_t)ii + 1] - mcy;
            float dz = cen[3 * (size_t)ii + 2] - mcz;
            float dist = sqrtf(dx * dx + dy * dy + dz * dz);
            bool a = dist <= THRF;
            g_act[ii] = a ? 1 : 0;
            if (a) lmx2 = fmaxf(lmx2, kp[ii]);
        }
        mx2 = wmaxf(lmx2);
        __syncwarp();
        float ld2 = 0.f; int lmi = M_ELEMS;
        bool any = false;
        for (int b = lane; b < cntv; b += 32) {
            int ii = g_idx[start + b];
            if (g_act[ii]) {
                any = true;
                float kk = kp[ii];
                ld2 += expf(kk - mx2);
                if (kk >= mx2) lmi = min(lmi, ii);
            }
        }
        d2 = wsumf(ld2);
        mi = wmini(lmi);
        actmask = __ballot_sync(FULL, any) ? 1u : 0u;
        if (!actmask) return;

        for (int b = 0; b < cntv; b++) {
            int ii = g_idx[start + b];
            if (!g_act[ii]) continue;
            float w = expf(kp[ii] - mx2);
            a0 = fmaf(__ldg(dense + (size_t)ii * 64 + lane),      w, a0);
            a1 = fmaf(__ldg(dense + (size_t)ii * 64 + 32 + lane), w, a1);
            a2 = fmaf(__ldg(p2 + (size_t)ii * st2), w, a2);
            a3 = fmaf(__ldg(p3 + (size_t)ii * st3), w, a3);
        }
    }

    if (lane == 0) { g_min[s] = mi; g_mx2[s] = mx2; }

    float inv2 = 1.0f / d2;   // d2 >= 1 when any active (max elt has e2=1)
    a0 *= inv2; a1 *= inv2; a2 *= inv2; a3 *= inv2;

    // rotation normalize: channels 88..91 = slot2 lanes 24..27
    float t = a2 * a2;
    t += __shfl_xor_sync(FULL, t, 1);
    t += __shfl_xor_sync(FULL, t, 2);
    if (lane >= 24 && lane < 28) {
        float n = sqrtf(t);
        a2 *= 1.0f / fmaxf(n, 1e-12f);
    }

    float* base = g_sums + (size_t)s * REC;
    base[lane]       = a0;
    base[32 + lane]  = a1;
    base[64 + lane]  = a2;
    if (lane < 10) base[96 + lane] = a3;
}

// ---------------- Pass 5: scatter outputs ----------------
__global__ void k_out(const float* __restrict__ dense, const float* __restrict__ cen,
                      const float* __restrict__ off,   const float* __restrict__ opa,
                      const float* __restrict__ sca,   const float* __restrict__ rot,
                      const float* __restrict__ fdc,   const float* __restrict__ kp,
                      const float* __restrict__ inst,  const float* __restrict__ mot,
                      const float* __restrict__ dyn,   const int* __restrict__ ids,
                      float* __restrict__ out) {
    int i = blockIdx.x * blockDim.x + threadIdx.x;
    if (i >= M_ELEMS) return;

    const size_t M = M_ELEMS;
    float* o_dense = out;
    float* o_cen   = out + 64 * M;
    float* o_off   = out + 67 * M;
    float* o_opa   = out + 70 * M;
    float* o_sca   = out + 71 * M;
    float* o_rot   = out + 74 * M;
    float* o_fdc   = out + 78 * M;
    float* o_kp    = out + 81 * M;
    float* o_inst  = out + 82 * M;
    float* o_mot   = out + 98 * M;
    float* o_dyn   = out + 106 * M;

    if (g_act[i]) {
        int seg = (i / VHW) * MAXID + ids[i];
        const float* r = g_sums + (size_t)seg * REC;
        float fac = (i == g_min[seg]) ? 1.0f : DUPF;

        float4* od = (float4*)(o_dense + (size_t)i * 64);
        const float4* rd = (const float4*)r;
#pragma unroll
        for (int k = 0; k < 16; k++) od[k] = rd[k];

        float4* oi = (float4*)(o_inst + (size_t)i * 16);
        const float4* ri = (const float4*)(r + 64);
#pragma unroll
        for (int k = 0; k < 4; k++) oi[k] = ri[k];

        float4* om = (float4*)(o_mot + (size_t)i * 8);
        const float4* rm = (const float4*)(r + 80);
        om[0] = rm[0]; om[1] = rm[1];

        ((float4*)(o_rot + (size_t)i * 4))[0] = ((const float4*)(r + 88))[0];

        o_cen[3 * (size_t)i + 0] = r[92];
        o_cen[3 * (size_t)i + 1] = r[93];
        o_cen[3 * (size_t)i + 2] = r[94];
        o_off[3 * (size_t)i + 0] = r[95];
        o_off[3 * (size_t)i + 1] = r[96];
        o_off[3 * (size_t)i + 2] = r[97];
        o_opa[i] = r[98] * fac;
        o_sca[3 * (size_t)i + 0] = r[99];
        o_sca[3 * (size_t)i + 1] = r[100];
        o_sca[3 * (size_t)i + 2] = r[101];
        o_fdc[3 * (size_t)i + 0] = r[102];
        o_fdc[3 * (size_t)i + 1] = r[103];
        o_fdc[3 * (size_t)i + 2] = r[104];
        o_kp[i]  = g_mx2[seg] * fac;
        o_dyn[i] = r[105];
    } else {
        float4* od = (float4*)(o_dense + (size_t)i * 64);
        const float4* sd = (const float4*)(dense + (size_t)i * 64);
#pragma unroll
        for (int k = 0; k < 16; k++) od[k] = sd[k];

        float4* oi = (float4*)(o_inst + (size_t)i * 16);
        const float4* si = (const float4*)(inst + (size_t)i * 16);
#pragma unroll
        for (int k = 0; k < 4; k++) oi[k] = si[k];

        float4* om = (float4*)(o_mot + (size_t)i * 8);
        const float4* sm = (const float4*)(mot + (size_t)i * 8);
        om[0] = sm[0]; om[1] = sm[1];

        ((float4*)(o_rot + (size_t)i * 4))[0] = ((const float4*)(rot + (size_t)i * 4))[0];

        o_cen[3 * (size_t)i + 0] = cen[3 * (size_t)i + 0];
        o_cen[3 * (size_t)i + 1] = cen[3 * (size_t)i + 1];
        o_cen[3 * (size_t)i + 2] = cen[3 * (size_t)i + 2];
        o_off[3 * (size_t)i + 0] = off[3 * (size_t)i + 0];
        o_off[3 * (size_t)i + 1] = off[3 * (size_t)i + 1];
        o_off[3 * (size_t)i + 2] = off[3 * (size_t)i + 2];
        o_opa[i] = opa[i];
        o_sca[3 * (size_t)i + 0] = sca[3 * (size_t)i + 0];
        o_sca[3 * (size_t)i + 1] = sca[3 * (size_t)i + 1];
        o_sca[3 * (size_t)i + 2] = sca[3 * (size_t)i + 2];
        o_fdc[3 * (size_t)i + 0] = fdc[3 * (size_t)i + 0];
        o_fdc[3 * (size_t)i + 1] = fdc[3 * (size_t)i + 1];
        o_fdc[3 * (size_t)i + 2] = fdc[3 * (size_t)i + 2];
        o_kp[i]  = kp[i];
        o_dyn[i] = dyn[i];
    }
}

extern "C" void kernel_launch(void* const* d_in, const int* in_sizes, int n_in,
                              void* d_out, int out_size) {
    const float* dense = (const float*)d_in[0];
    const float* cen   = (const float*)d_in[1];
    const float* off   = (const float*)d_in[2];
    const float* opa   = (const float*)d_in[3];
    const float* sca   = (const float*)d_in[4];
    const float* rot   = (const float*)d_in[5];
    const float* fdc   = (const float*)d_in[6];
    const float* kp    = (const float*)d_in[7];
    const float* inst  = (const float*)d_in[8];
    const float* mot   = (const float*)d_in[9];
    const float* dyn   = (const float*)d_in[10];
    const int*   ids   = (const int*)d_in[11];
    float* out = (float*)d_out;

    const int TB = 256;
    const int gM = (M_ELEMS + TB - 1) / TB;
    const int gS = (NSEGS + TB - 1) / TB;
    const int gW = (NSEGS * 32 + TB - 1) / TB;   // warp per segment

    k_zero<<<gS, TB>>>();
    k_count<<<gM, TB>>>(ids);
    k_scan<<<1, 1024>>>();
    k_scatter<<<gM, TB>>>(ids);
    k_merge<<<gW, TB>>>(dense, cen, off, opa, sca, rot, fdc, kp, inst, mot, dyn);
    k_out<<<gM, TB>>>(dense, cen, off, opa, sca, rot, fdc, kp, inst, mot, dyn, ids, out);
}

// round 3
// speedup vs baseline: 1.1547x; 1.1547x over previous
#include <cuda_runtime.h>

// Fixed problem shape: B=1, T=4, V=6, H=128, W=128
#define MAXID    8192
#define BT       4
#define M_ELEMS  393216
#define VHW      (M_ELEMS / BT)       // 98304
#define NSEGS    (BT * MAXID)         // 32768
#define REC      112                  // per-segment record (floats), 448B
#define NEGF     (-1e30f)
#define THRF     2.0f
#define DUPF     0.05f

// Record layout (float slots):
//  [0..63] dense  [64..79] inst  [80..87] motion  [88..91] rot
//  [92..94] center [95..97] offset [98] opacity [99..101] scale
//  [102..104] feat_dc [105] dyn [106] d2 (sum e2) [107..111] pad

__device__ int           g_cnt[NSEGS];
__device__ float4        g_e1c[NSEGS];           // {d1, sum(cen*e1).xyz}
__device__ float         g_mx2[NSEGS];
__device__ int           g_min[NSEGS];
__device__ unsigned char g_act[M_ELEMS];
__device__ __align__(16) float g_sums[(size_t)NSEGS * REC];

__device__ __forceinline__ void atomicMaxF(float* addr, float v) {
    if (v >= 0.0f) atomicMax((int*)addr, __float_as_int(v));
    else           atomicMin((unsigned int*)addr, __float_as_uint(v));
}
__device__ __forceinline__ void red4(float* addr, float a, float b, float c, float d) {
    asm volatile("red.global.add.v4.f32 [%0], {%1,%2,%3,%4};"
                 :: "l"(addr), "f"(a), "f"(b), "f"(c), "f"(d) : "memory");
}

// ---------------- Pass 0: init scratch (vectorized) ----------------
#define SUMS4 (NSEGS * REC / 4)       // 917504 float4 stores
__global__ void k_init() {
    int t = blockIdx.x * blockDim.x + threadIdx.x;
    if (t < SUMS4) ((float4*)g_sums)[t] = make_float4(0.f, 0.f, 0.f, 0.f);
    if (t < NSEGS) {
        g_cnt[t] = 0;
        g_e1c[t] = make_float4(0.f, 0.f, 0.f, 0.f);
        g_mx2[t] = NEGF;
        g_min[t] = M_ELEMS;
    }
}

// ---------------- Pass 1: count + e1/cen*e1 accumulate (4 elems/thread) ----
__global__ void k_p12(const int* __restrict__ ids, const float* __restrict__ kp,
                      const float* __restrict__ cen) {
    int base = (blockIdx.x * blockDim.x + threadIdx.x) * 4;
    if (base >= M_ELEMS) return;
    int4   id4 = *(const int4*)(ids + base);
    float4 k4  = *(const float4*)(kp + base);
    // 12 center floats for the 4 elements
    float4 c0 = *(const float4*)(cen + (size_t)base * 3);
    float4 c1 = *(const float4*)(cen + (size_t)base * 3 + 4);
    float4 c2 = *(const float4*)(cen + (size_t)base * 3 + 8);
    int bt = base / VHW;   // 4 consecutive elems never straddle a VHW boundary (VHW%4==0)

    int   idv[4] = {id4.x, id4.y, id4.z, id4.w};
    float kv[4]  = {k4.x, k4.y, k4.z, k4.w};
    float cx[4] = {c0.x, c0.w, c1.z, c2.y};
    float cy[4] = {c0.y, c1.x, c1.w, c2.z};
    float cz[4] = {c0.z, c1.y, c2.x, c2.w};
#pragma unroll
    for (int j = 0; j < 4; j++) {
        if (idv[j] >= 0) {
            int seg = bt * MAXID + idv[j];
            float e1 = expf(kv[j]);
            atomicAdd(&g_cnt[seg], 1);
            red4((float*)&g_e1c[seg], e1, cx[j] * e1, cy[j] * e1, cz[j] * e1);
        }
    }
}

// ---------------- Pass 2: active mask + exact max2 (4 elems/thread) -------
__global__ void k_p3(const int* __restrict__ ids, const float* __restrict__ kp,
                     const float* __restrict__ cen) {
    int base = (blockIdx.x * blockDim.x + threadIdx.x) * 4;
    if (base >= M_ELEMS) return;
    int4   id4 = *(const int4*)(ids + base);
    float4 k4  = *(const float4*)(kp + base);
    float4 c0 = *(const float4*)(cen + (size_t)base * 3);
    float4 c1 = *(const float4*)(cen + (size_t)base * 3 + 4);
    float4 c2 = *(const float4*)(cen + (size_t)base * 3 + 8);
    int bt = base / VHW;

    int   idv[4] = {id4.x, id4.y, id4.z, id4.w};
    float kv[4]  = {k4.x, k4.y, k4.z, k4.w};
    float cx[4] = {c0.x, c0.w, c1.z, c2.y};
    float cy[4] = {c0.y, c1.x, c1.w, c2.z};
    float cz[4] = {c0.z, c1.y, c2.x, c2.w};

    uchar4 act = make_uchar4(0, 0, 0, 0);
    unsigned char* av = (unsigned char*)&act;
#pragma unroll
    for (int j = 0; j < 4; j++) {
        if (idv[j] >= 0) {
            int seg = bt * MAXID + idv[j];
            if (__ldg(&g_cnt[seg]) >= 2) {
                float4 f = __ldg(&g_e1c[seg]);
                float inv = (f.x > 0.0f) ? (1.0f / f.x) : 1.0f;
                float dx = cx[j] - f.y * inv;
                float dy = cy[j] - f.z * inv;
                float dz = cz[j] - f.w * inv;
                float dist = sqrtf(dx * dx + dy * dy + dz * dz);
                if (dist <= THRF) {
                    av[j] = 1;
                    atomicMaxF(&g_mx2[seg], kv[j]);
                }
            }
        }
    }
    *(uchar4*)(g_act + base) = act;
}

// ---------------- Pass 3: big weighted accumulate (v4 reds) ----------------
__global__ void k_p4(const float* __restrict__ dense, const float* __restrict__ cen,
                     const float* __restrict__ off,   const float* __restrict__ opa,
                     const float* __restrict__ sca,   const float* __restrict__ rot,
                     const float* __restrict__ fdc,   const float* __restrict__ kp,
                     const float* __restrict__ inst,  const float* __restrict__ mot,
                     const float* __restrict__ dyn,   const int* __restrict__ ids) {
    int i = blockIdx.x * blockDim.x + threadIdx.x;
    if (i >= M_ELEMS) return;
    if (!g_act[i]) return;

    int seg = (i / VHW) * MAXID + ids[i];
    float k0 = kp[i];
    float e2 = expf(k0);
    if (k0 >= __ldg(&g_mx2[seg])) atomicMin(&g_min[seg], i);

    float* base = g_sums + (size_t)seg * REC;

    const float4* dv = (const float4*)(dense + (size_t)i * 64);
#pragma unroll
    for (int k = 0; k < 16; k++) {
        float4 v = dv[k];
        red4(base + 4 * k, v.x * e2, v.y * e2, v.z * e2, v.w * e2);
    }
    const float4* iv = (const float4*)(inst + (size_t)i * 16);
#pragma unroll
    for (int k = 0; k < 4; k++) {
        float4 v = iv[k];
        red4(base + 64 + 4 * k, v.x * e2, v.y * e2, v.z * e2, v.w * e2);
    }
    const float4* mv = (const float4*)(mot + (size_t)i * 8);
#pragma unroll
    for (int k = 0; k < 2; k++) {
        float4 v = mv[k];
        red4(base + 80 + 4 * k, v.x * e2, v.y * e2, v.z * e2, v.w * e2);
    }
    {
        float4 v = ((const float4*)(rot + (size_t)i * 4))[0];
        red4(base + 88, v.x * e2, v.y * e2, v.z * e2, v.w * e2);
    }
    float c0 = cen[3 * (size_t)i], c1 = cen[3 * (size_t)i + 1], c2 = cen[3 * (size_t)i + 2];
    float o0 = off[3 * (size_t)i], o1 = off[3 * (size_t)i + 1], o2 = off[3 * (size_t)i + 2];
    float op = opa[i];
    float s0 = sca[3 * (size_t)i], s1 = sca[3 * (size_t)i + 1], s2 = sca[3 * (size_t)i + 2];
    float f0 = fdc[3 * (size_t)i], f1 = fdc[3 * (size_t)i + 1], f2 = fdc[3 * (size_t)i + 2];
    float dn = dyn[i];
    red4(base + 92,  c0 * e2, c1 * e2, c2 * e2, o0 * e2);
    red4(base + 96,  o1 * e2, o2 * e2, op * e2, s0 * e2);
    red4(base + 100, s1 * e2, s2 * e2, f0 * e2, f1 * e2);
    red4(base + 104, f2 * e2, dn * e2, e2,      0.0f);
}

// ---------------- Pass 4: scatter outputs (divide + rot-norm inline) -------
__global__ void k_out(const float* __restrict__ dense, const float* __restrict__ cen,
                      const float* __restrict__ off,   const float* __restrict__ opa,
                      const float* __restrict__ sca,   const float* __restrict__ rot,
                      const float* __restrict__ fdc,   const float* __restrict__ kp,
                      const float* __restrict__ inst,  const float* __restrict__ mot,
                      const float* __restrict__ dyn,   const int* __restrict__ ids,
                      float* __restrict__ out) {
    int i = blockIdx.x * blockDim.x + threadIdx.x;
    if (i >= M_ELEMS) return;

    const size_t M = M_ELEMS;
    float* o_dense = out;
    float* o_cen   = out + 64 * M;
    float* o_off   = out + 67 * M;
    float* o_opa   = out + 70 * M;
    float* o_sca   = out + 71 * M;
    float* o_rot   = out + 74 * M;
    float* o_fdc   = out + 78 * M;
    float* o_kp    = out + 81 * M;
    float* o_inst  = out + 82 * M;
    float* o_mot   = out + 98 * M;
    float* o_dyn   = out + 106 * M;

    if (g_act[i]) {
        int seg = (i / VHW) * MAXID + ids[i];
        const float* r = g_sums + (size_t)seg * REC;
        float d2  = __ldg(r + 106);
        float inv = 1.0f / d2;           // element is active => d2 >= exp(k0) > 0
        float fac = (i == __ldg(&g_min[seg])) ? 1.0f : DUPF;

        float4* od = (float4*)(o_dense + (size_t)i * 64);
        const float4* rd = (const float4*)r;
#pragma unroll
        for (int k = 0; k < 16; k++) {
            float4 v = rd[k];
            od[k] = make_float4(v.x * inv, v.y * inv, v.z * inv, v.w * inv);
        }
        float4* oi = (float4*)(o_inst + (size_t)i * 16);
        const float4* ri = (const float4*)(r + 64);
#pragma unroll
        for (int k = 0; k < 4; k++) {
            float4 v = ri[k];
            oi[k] = make_float4(v.x * inv, v.y * inv, v.z * inv, v.w * inv);
        }
        float4* om = (float4*)(o_mot + (size_t)i * 8);
        const float4* rm = (const float4*)(r + 80);
#pragma unroll
        for (int k = 0; k < 2; k++) {
            float4 v = rm[k];
            om[k] = make_float4(v.x * inv, v.y * inv, v.z * inv, v.w * inv);
        }
        {   // rotation: divide by d2 then normalize (matches reference order)
            float4 q = ((const float4*)(r + 88))[0];
            q.x *= inv; q.y *= inv; q.z *= inv; q.w *= inv;
            float n = sqrtf(q.x * q.x + q.y * q.y + q.z * q.z + q.w * q.w);
            float qi = 1.0f / fmaxf(n, 1e-12f);
            ((float4*)(o_rot + (size_t)i * 4))[0] =
                make_float4(q.x * qi, q.y * qi, q.z * qi, q.w * qi);
        }
        o_cen[3 * (size_t)i + 0] = r[92] * inv;
        o_cen[3 * (size_t)i + 1] = r[93] * inv;
        o_cen[3 * (size_t)i + 2] = r[94] * inv;
        o_off[3 * (size_t)i + 0] = r[95] * inv;
        o_off[3 * (size_t)i + 1] = r[96] * inv;
        o_off[3 * (size_t)i + 2] = r[97] * inv;
        o_opa[i] = r[98] * inv * fac;
        o_sca[3 * (size_t)i + 0] = r[99]  * inv;
        o_sca[3 * (size_t)i + 1] = r[100] * inv;
        o_sca[3 * (size_t)i + 2] = r[101] * inv;
        o_fdc[3 * (size_t)i + 0] = r[102] * inv;
        o_fdc[3 * (size_t)i + 1] = r[103] * inv;
        o_fdc[3 * (size_t)i + 2] = r[104] * inv;
        o_kp[i]  = __ldg(&g_mx2[seg]) * fac;
        o_dyn[i] = r[105] * inv;
    } else {
        float4* od = (float4*)(o_dense + (size_t)i * 64);
        const float4* sd = (const float4*)(dense + (size_t)i * 64);
#pragma unroll
        for (int k = 0; k < 16; k++) od[k] = sd[k];

        float4* oi = (float4*)(o_inst + (size_t)i * 16);
        const float4* si = (const float4*)(inst + (size_t)i * 16);
#pragma unroll
        for (int k = 0; k < 4; k++) oi[k] = si[k];

        float4* om = (float4*)(o_mot + (size_t)i * 8);
        const float4* sm = (const float4*)(mot + (size_t)i * 8);
        om[0] = sm[0]; om[1] = sm[1];

        ((float4*)(o_rot + (size_t)i * 4))[0] = ((const float4*)(rot + (size_t)i * 4))[0];

        o_cen[3 * (size_t)i + 0] = cen[3 * (size_t)i + 0];
        o_cen[3 * (size_t)i + 1] = cen[3 * (size_t)i + 1];
        o_cen[3 * (size_t)i + 2] = cen[3 * (size_t)i + 2];
        o_off[3 * (size_t)i + 0] = off[3 * (size_t)i + 0];
        o_off[3 * (size_t)i + 1] = off[3 * (size_t)i + 1];
        o_off[3 * (size_t)i + 2] = off[3 * (size_t)i + 2];
        o_opa[i] = opa[i];
        o_sca[3 * (size_t)i + 0] = sca[3 * (size_t)i + 0];
        o_sca[3 * (size_t)i + 1] = sca[3 * (size_t)i + 1];
        o_sca[3 * (size_t)i + 2] = sca[3 * (size_t)i + 2];
        o_fdc[3 * (size_t)i + 0] = fdc[3 * (size_t)i + 0];
        o_fdc[3 * (size_t)i + 1] = fdc[3 * (size_t)i + 1];
        o_fdc[3 * (size_t)i + 2] = fdc[3 * (size_t)i + 2];
        o_kp[i]  = kp[i];
        o_dyn[i] = dyn[i];
    }
}

extern "C" void kernel_launch(void* const* d_in, const int* in_sizes, int n_in,
                              void* d_out, int out_size) {
    const float* dense = (const float*)d_in[0];
    const float* cen   = (const float*)d_in[1];
    const float* off   = (const float*)d_in[2];
    const float* opa   = (const float*)d_in[3];
    const float* sca   = (const float*)d_in[4];
    const float* rot   = (const float*)d_in[5];
    const float* fdc   = (const float*)d_in[6];
    const float* kp    = (const float*)d_in[7];
    const float* inst  = (const float*)d_in[8];
    const float* mot   = (const float*)d_in[9];
    const float* dyn   = (const float*)d_in[10];
    const int*   ids   = (const int*)d_in[11];
    float* out = (float*)d_out;

    const int TB = 256;
    const int gI = (SUMS4 + TB - 1) / TB;
    const int gM = (M_ELEMS + TB - 1) / TB;
    const int g4 = (M_ELEMS / 4 + TB - 1) / TB;

    k_init<<<gI, TB>>>();
    k_p12<<<g4, TB>>>(ids, kp, cen);
    k_p3 <<<g4, TB>>>(ids, kp, cen);
    k_p4 <<<gM, TB>>>(dense, cen, off, opa, sca, rot, fdc, kp, inst, mot, dyn, ids);
    k_out<<<gM, TB>>>(dense, cen, off, opa, sca, rot, fdc, kp, inst, mot, dyn, ids, out);
}